// round 2
// baseline (speedup 1.0000x reference)
#include <cuda_runtime.h>
#include <stdint.h>

// Embedding gather: out[j*64+k] = pages[idx[j]*64+k]
// pages layout [8,125000,64] contiguous; (i/P)*P + i%P == i, so the
// two-level page/row gather collapses to a flat gather at element idx[j]*64.
//
// indices are int32 (JAX default x64-disabled downcasts the requested int64).
//
// One float4 (16 B) per thread; 16 threads cover one 256 B row, so each
// lookup's read is two fully-used 128 B lines. The idx load is uniform
// across the 16-thread group (L1 broadcast).

#define N_WORDS 1000000LL

__global__ void emb_gather_kernel(const int* __restrict__ idx,
                                  const float4* __restrict__ pages4,
                                  float4* __restrict__ out4,
                                  long long n_vec) {
    long long t = (long long)blockIdx.x * blockDim.x + threadIdx.x;
    if (t >= n_vec) return;
    long long j = t >> 4;          // lookup id
    int c = (int)(t & 15);         // float4 slot within the 64-float row
    long long i = (long long)__ldg(&idx[j]);
    // Defensive clamp: no-op for valid data, prevents illegal access if the
    // dtype assumption is ever wrong (turns a crash into a visible rel_err).
    if (i < 0) i = 0;
    if (i >= N_WORDS) i = N_WORDS - 1;
    out4[t] = __ldg(&pages4[i * 16 + c]);
}

extern "C" void kernel_launch(void* const* d_in, const int* in_sizes, int n_in,
                              void* d_out, int out_size) {
    const int*   idx   = (const int*)d_in[0];    // indices [16,8192] (int32)
    const float* pages = (const float*)d_in[1];  // [8,125000,64] fp32

    long long n_lookups = in_sizes[0];  // 131072
    long long n_vec = n_lookups * 16;   // float4s in output

    int threads = 256;
    long long blocks = (n_vec + threads - 1) / threads;

    emb_gather_kernel<<<(unsigned)blocks, threads>>>(
        idx, (const float4*)pages, (float4*)d_out, n_vec);
}

// round 4
// speedup vs baseline: 1.1756x; 1.1756x over previous
#include <cuda_runtime.h>
#include <stdint.h>

// Embedding gather: out[j*64+k] = pages[idx[j]*64+k]
// pages [8,125000,64] contiguous; (i/P)*P + i%P == i -> flat gather at idx[j]*64.
// indices are int32 (JAX default x64-disabled).
//
// ILP=4: each thread moves 4 float4s (grid-strided, coalesced within each
// batch). All idx loads issue first, then 4 independent table gathers ->
// per-thread MLP=4+, hiding DRAM/L2 latency that bound the previous version.
// Output uses evict-first streaming stores so the 32 MB of writes don't evict
// the table working set (~33 MB, replay-resident) from L2.

#define N_WORDS 1000000
#define ILP 4

__global__ void __launch_bounds__(256) emb_gather_kernel(
        const int* __restrict__ idx,
        const float4* __restrict__ pages4,
        float4* __restrict__ out4,
        long long n_vec) {
    const long long S = (long long)gridDim.x * blockDim.x;  // threads total
    long long t = (long long)blockIdx.x * blockDim.x + threadIdx.x;

    long long tt[ILP];
    long long base[ILP];
    int c[ILP];
    bool ok[ILP];

    // Phase 1: all index loads (independent, issue back-to-back)
    #pragma unroll
    for (int u = 0; u < ILP; u++) {
        tt[u] = t + (long long)u * S;
        ok[u] = (tt[u] < n_vec);
        long long j = tt[u] >> 4;
        c[u] = (int)(tt[u] & 15);
        int iv = ok[u] ? __ldg(&idx[j]) : 0;
        // defensive clamp (no-op on valid data; 1 IMNMX pair)
        iv = max(0, min(iv, N_WORDS - 1));
        base[u] = (long long)iv * 16 + c[u];
    }

    // Phase 2: all table gathers (independent -> MLP=4)
    float4 d[ILP];
    #pragma unroll
    for (int u = 0; u < ILP; u++) {
        d[u] = ok[u] ? __ldg(&pages4[base[u]]) : make_float4(0.f, 0.f, 0.f, 0.f);
    }

    // Phase 3: streaming stores (evict-first; don't pollute L2)
    #pragma unroll
    for (int u = 0; u < ILP; u++) {
        if (ok[u]) __stcs(&out4[tt[u]], d[u]);
    }
}

extern "C" void kernel_launch(void* const* d_in, const int* in_sizes, int n_in,
                              void* d_out, int out_size) {
    const int*   idx   = (const int*)d_in[0];    // [16,8192] int32
    const float* pages = (const float*)d_in[1];  // [8,125000,64] fp32

    long long n_lookups = in_sizes[0];        // 131072
    long long n_vec = n_lookups * 16;         // 2,097,152 float4s

    const int threads = 256;
    long long total_threads = (n_vec + ILP - 1) / ILP;
    int blocks = (int)((total_threads + threads - 1) / threads);  // 2048

    emb_gather_kernel<<<blocks, threads>>>(
        idx, (const float4*)pages, (float4*)d_out, n_vec);
}